// round 16
// baseline (speedup 1.0000x reference)
#include <cuda_runtime.h>
#include <cuda_fp16.h>
#include <cstdint>

#define B_  128
#define T_  2048
#define H_  200
#define HP  208
#define LD  216
#define G4  800
#define NCHUNK 64        // context chunks per batch (32 t each)

// ---------------- device scratch ----------------
__device__ __align__(16) half g_Ua[HP * LD];
__device__ float g_qadd[B_ * HP];
__device__ float g_hpre[B_ * G4];
__device__ float g_sc0[B_ * T_];               // scores partial n-half 0 (+bva) -> att (normalized)
__device__ float g_sc1[B_ * T_];               // scores partial n-half 1
__device__ float g_ctxp[NCHUNK * B_ * H_];     // context partials
__device__ float g_gb[B_ * G4];                // gates base

// ---------------- helpers ----------------
__device__ __forceinline__ uint32_t smem_u32(const void* p) {
    uint32_t a;
    asm("{ .reg .u64 t; cvta.to.shared.u64 t, %1; cvt.u32.u64 %0, t; }" : "=r"(a) : "l"(p));
    return a;
}
__device__ __forceinline__ void ldsm4(uint32_t* r, uint32_t addr) {
    asm volatile("ldmatrix.sync.aligned.m8n8.x4.shared.b16 {%0,%1,%2,%3}, [%4];"
                 : "=r"(r[0]), "=r"(r[1]), "=r"(r[2]), "=r"(r[3]) : "r"(addr));
}
__device__ __forceinline__ void mma16816(float* d, const uint32_t* a, uint32_t b0, uint32_t b1) {
    asm volatile("mma.sync.aligned.m16n8k16.row.col.f32.f16.f16.f32 "
                 "{%0,%1,%2,%3}, {%4,%5,%6,%7}, {%8,%9}, {%0,%1,%2,%3};"
                 : "+f"(d[0]), "+f"(d[1]), "+f"(d[2]), "+f"(d[3])
                 : "r"(a[0]), "r"(a[1]), "r"(a[2]), "r"(a[3]), "r"(b0), "r"(b1));
}
__device__ __forceinline__ float tanh_fast(float x) {
    float y;
    asm("tanh.approx.f32 %0, %1;" : "=f"(y) : "f"(x));
    return y;
}
__device__ __forceinline__ float fast_sig(float x) {
    return __fdividef(1.f, 1.f + __expf(-x));
}
__device__ __forceinline__ float ref_tanh(float x) {
    float e = __expf(2.f * x);
    return 1.f - __fdividef(2.f, e + 1.f);
}
__device__ __forceinline__ float wred(float v) {
    v += __shfl_xor_sync(~0u, v, 16); v += __shfl_xor_sync(~0u, v, 8);
    v += __shfl_xor_sync(~0u, v, 4);  v += __shfl_xor_sync(~0u, v, 2);
    v += __shfl_xor_sync(~0u, v, 1);  return v;
}
__device__ __forceinline__ float qred(float v) {
    v += __shfl_xor_sync(~0u, v, 1);
    v += __shfl_xor_sync(~0u, v, 2);
    v += __shfl_xor_sync(~0u, v, 4);
    return v;
}

// -------- prep (merged): blocks 0..207 lay out Ua; blocks 208..335 do qadd+h_pre --------
__global__ void __launch_bounds__(512) prep_k(const float* __restrict__ Ua,
                                              const float* __restrict__ h0,
                                              const float* __restrict__ Wa,
                                              const float* __restrict__ ba,
                                              const float* __restrict__ bua,
                                              const float* __restrict__ Whh,
                                              const float* __restrict__ bhh) {
    int blk = blockIdx.x, tid = threadIdx.x;
    if (blk < HP) {
        int n = blk;
        if (tid < LD) {
            float v = (n < H_ && tid < H_) ? Ua[n * H_ + tid] : 0.f;
            g_Ua[n * LD + tid] = __float2half(v);
        }
        return;
    }
    int b = blk - HP, wid = tid >> 5, lid = tid & 31;
    __shared__ float hs[H_];
    if (tid < H_) hs[tid] = h0[b * H_ + tid];
    __syncthreads();
    for (int r = wid; r < HP; r += 16) {
        float acc = 0.f;
        if (r < H_) {
            const float* w = Wa + r * H_;
            #pragma unroll
            for (int k = lid; k < H_; k += 32) acc += hs[k] * w[k];
        }
        acc = wred(acc);
        if (lid == 0) g_qadd[b * HP + r] = (r < H_) ? acc + ba[r] + bua[r] : 0.f;
    }
    for (int r = wid; r < G4; r += 16) {
        const float* w = Whh + r * H_;
        float acc = 0.f;
        #pragma unroll
        for (int k = lid; k < H_; k += 32) acc += hs[k] * w[k];
        acc = wred(acc);
        if (lid == 0) g_hpre[b * G4 + r] = acc + bhh[r];
    }
}

// -------- scores: two-phase smem + N-split -> 3 CTAs/SM --------
#define SMREG   55296
#define SM_QV2  SMREG
#define SM2_TOT (SMREG + HP * 8 + 64)

__global__ void __launch_bounds__(256, 3) scores_k(const float* __restrict__ enc,
                                                   const float* __restrict__ Va,
                                                   const float* __restrict__ bva) {
    extern __shared__ char sm[];
    half*   Reg = (half*)sm;
    float2* qv  = (float2*)(sm + SM_QV2);

    int tid = threadIdx.x, wid = tid >> 5, lid = tid & 31;
    int bidx = blockIdx.x;
    int nh = bidx & 1;
    int tt = (bidx >> 1) & 15;
    int b  = bidx >> 5;
    int t0 = tt << 7;
    int n0 = nh ? 112 : 0;
    int np = nh ? 6 : 7;

    const float* encb = enc + (size_t)(b * T_ + t0) * H_;
    for (int u = tid; u < 128 * 27; u += 256) {
        int row = u / 27, oc = u % 27, k = oc * 8;
        uint4 v;
        half2* hp = (half2*)&v;
        if (k < H_) {
            const float4 f0 = *(const float4*)(encb + row * H_ + k);
            const float4 f1 = *(const float4*)(encb + row * H_ + k + 4);
            hp[0] = __floats2half2_rn(f0.x, f0.y);
            hp[1] = __floats2half2_rn(f0.z, f0.w);
            hp[2] = __floats2half2_rn(f1.x, f1.y);
            hp[3] = __floats2half2_rn(f1.z, f1.w);
        } else {
            v = make_uint4(0, 0, 0, 0);
        }
        *(uint4*)(Reg + row * LD + k) = v;
    }
    if (tid < HP) qv[tid] = make_float2(g_qadd[b * HP + tid], (tid < H_) ? Va[tid] : 0.f);
    __syncthreads();

    int lr = lid & 7, quad = lid >> 3;
    uint32_t a_base = smem_u32(Reg) + (uint32_t)(((wid * 16) + (quad & 1) * 8 + lr) * LD + (quad >> 1) * 8) * 2u;
    uint32_t afr[13][4];
    #pragma unroll
    for (int s = 0; s < 13; s++) ldsm4(afr[s], a_base + (uint32_t)(s * 32));
    __syncthreads();

    {
        const uint4* s4 = (const uint4*)(g_Ua + n0 * LD);
        uint4* d4 = (uint4*)Reg;
        int cnt = np * 16 * 27;
        for (int i = tid; i < cnt; i += 256) d4[i] = s4[i];
    }
    __syncthreads();

    uint32_t b_base = smem_u32(Reg) + (uint32_t)((((quad >> 1) * 8) + lr) * LD + (quad & 1) * 8) * 2u;
    float pA = 0.f, pB = 0.f;
    int cq = (lid & 3) * 2;

    for (int pl = 0; pl < np; pl++) {
        float a0[4] = {0.f, 0.f, 0.f, 0.f};
        float a1[4] = {0.f, 0.f, 0.f, 0.f};
        float a2[4] = {0.f, 0.f, 0.f, 0.f};
        float a3[4] = {0.f, 0.f, 0.f, 0.f};
        uint32_t bp = b_base + (uint32_t)(pl * 16 * LD * 2);
        #pragma unroll
        for (int s = 0; s < 13; s++) {
            uint32_t bb[4];
            ldsm4(bb, bp + (uint32_t)(s * 32));
            if (s < 7) {
                mma16816(a0, afr[s], bb[0], bb[1]);
                mma16816(a1, afr[s], bb[2], bb[3]);
            } else {
                mma16816(a2, afr[s], bb[0], bb[1]);
                mma16816(a3, afr[s], bb[2], bb[3]);
            }
        }
        int n = n0 + pl * 16 + cq;
        float2 q0 = qv[n],     q1 = qv[n + 1];
        float2 q2 = qv[n + 8], q3 = qv[n + 9];
        pA += q0.y * tanh_fast(q0.x + a0[0] + a2[0]);
        pA += q1.y * tanh_fast(q1.x + a0[1] + a2[1]);
        pB += q0.y * tanh_fast(q0.x + a0[2] + a2[2]);
        pB += q1.y * tanh_fast(q1.x + a0[3] + a2[3]);
        pA += q2.y * tanh_fast(q2.x + a1[0] + a3[0]);
        pA += q3.y * tanh_fast(q3.x + a1[1] + a3[1]);
        pB += q2.y * tanh_fast(q2.x + a1[2] + a3[2]);
        pB += q3.y * tanh_fast(q3.x + a1[3] + a3[3]);
    }

    pA += __shfl_xor_sync(~0u, pA, 1); pA += __shfl_xor_sync(~0u, pA, 2);
    pB += __shfl_xor_sync(~0u, pB, 1); pB += __shfl_xor_sync(~0u, pB, 2);
    if ((lid & 3) == 0) {
        int r = lid >> 2;
        float bv = nh ? 0.f : bva[0];
        float* dst = nh ? g_sc1 : g_sc0;
        dst[b * T_ + t0 + wid * 16 + r]     = pA + bv;
        dst[b * T_ + t0 + wid * 16 + r + 8] = pB + bv;
    }
}

// -------- softmax over T per batch: att = softmax(sc0+sc1) -> g_sc0 --------
__global__ void softmax_k() {
    int b = blockIdx.x, tid = threadIdx.x;
    __shared__ float red[256];
    float* s0 = g_sc0 + b * T_;
    float* s1 = g_sc1 + b * T_;
    float v[8], m = -1e30f;
    #pragma unroll
    for (int i = 0; i < 8; i++) {
        v[i] = s0[tid + i * 256] + s1[tid + i * 256];
        m = fmaxf(m, v[i]);
    }
    red[tid] = m; __syncthreads();
    for (int st = 128; st > 0; st >>= 1) { if (tid < st) red[tid] = fmaxf(red[tid], red[tid + st]); __syncthreads(); }
    m = red[0]; __syncthreads();
    float sum = 0.f;
    #pragma unroll
    for (int i = 0; i < 8; i++) { v[i] = __expf(v[i] - m); sum += v[i]; }
    red[tid] = sum; __syncthreads();
    for (int st = 128; st > 0; st >>= 1) { if (tid < st) red[tid] += red[tid + st]; __syncthreads(); }
    float inv = 1.f / red[0];
    #pragma unroll
    for (int i = 0; i < 8; i++) s0[tid + i * 256] = v[i] * inv;
}

// -------- context partials: 8192 CTAs (128 b x 64 chunks of 32 t) --------
// 512 threads: two 256-thread halves cover 16 t-rows each, fully unrolled.
__global__ void __launch_bounds__(512) ctx_k(const float* __restrict__ enc) {
    __shared__ float att[32];
    __shared__ float part[2][H_];
    int b = blockIdx.x, s = blockIdx.y;
    int tid = threadIdx.x;
    if (tid < 32) att[tid] = g_sc0[b * T_ + s * 32 + tid];
    __syncthreads();
    int half = tid >> 8, th = tid & 255;
    if (th < H_) {
        const float* p = enc + ((size_t)(b * T_ + s * 32 + half * 16)) * H_ + th;
        const float* aw = att + half * 16;
        float acc = 0.f;
        #pragma unroll
        for (int t = 0; t < 16; t++) acc += aw[t] * p[(size_t)t * H_];
        part[half][th] = acc;
    }
    __syncthreads();
    if (tid < H_)
        g_ctxp[(s * B_ + b) * H_ + tid] = part[0][tid] + part[1][tid];
}

// -------- gates base: 1024 CTAs (128 b x 8 slices of 100 rows) --------
__global__ void __launch_bounds__(256) gates_k(const float* __restrict__ Wih,
                                               const float* __restrict__ bih) {
    int b = blockIdx.x, slice = blockIdx.y;
    int tid = threadIdx.x, wid = tid >> 5, lid = tid & 31;
    __shared__ float ctx[H_];
    if (tid < H_) {
        float a = 0.f;
        #pragma unroll
        for (int j = 0; j < NCHUNK; j++) a += g_ctxp[(j * B_ + b) * H_ + tid];
        ctx[tid] = a;
    }
    __syncthreads();
    int g0 = slice * 100;
    for (int r = wid; r < 100; r += 8) {
        int g = g0 + r;
        const float* w = Wih + (size_t)g * 201 + 1;
        float acc = 0.f;
        #pragma unroll
        for (int k = lid; k < H_; k += 32) acc += ctx[k] * w[k];
        acc = wred(acc);
        if (lid == 0) g_gb[b * G4 + g] = acc + bih[g] + g_hpre[b * G4 + g];
    }
}

// -------- decoder: 5 steps only, weights in smem, gates base precomputed --------
#define DW1   0
#define DW2   (100 * 200)
#define DW3   (DW2 + 50 * 104)
#define DSM_FLOATS (DW3 + 64)
#define DSM_TOT (DSM_FLOATS * 4)

__global__ void __launch_bounds__(512) decoder_k(
                          const float* __restrict__ x,  const float* __restrict__ c0,
                          const float* __restrict__ Wih,
                          const float* __restrict__ W1, const float* __restrict__ b1,
                          const float* __restrict__ W2, const float* __restrict__ b2,
                          const float* __restrict__ W3, const float* __restrict__ b3,
                          float* __restrict__ out) {
    extern __shared__ float dsm[];
    __shared__ float gb[G4], wcol[G4], c0s[H_], r0s[H_];
    __shared__ float l1s[100], l2s[52], b1s[100], b2s[52];
    __shared__ float xs, b3s;

    int b = blockIdx.x, tid = threadIdx.x, wid = tid >> 5, lid = tid & 31;
    int q = lid >> 3, kl = lid & 7;

    {
        const float4* s4 = (const float4*)W1;
        float4* d4 = (float4*)(dsm + DW1);
        for (int i = tid; i < 5000; i += 512) d4[i] = s4[i];
    }
    for (int i = tid; i < 5000; i += 512) {
        int r = i / 100, c = i % 100;
        dsm[DW2 + r * 104 + c] = W2[i];
    }
    if (tid < 50)  { dsm[DW3 + tid] = W3[tid]; b2s[tid] = b2[tid]; }
    if (tid < 100) b1s[tid] = b1[tid];
    if (tid < H_) c0s[tid] = c0[b * H_ + tid];
    if (tid == 0) { xs = x[b]; b3s = b3[0]; }
    for (int g = tid; g < G4; g += 512) {
        gb[g]   = g_gb[b * G4 + g];
        wcol[g] = Wih[g * 201];
    }
    __syncthreads();

    float xv = xs;
    for (int st = 0; st < 5; st++) {
        if (tid < H_) {
            float gi = gb[tid]          + xv * wcol[tid];
            float gf = gb[H_ + tid]     + xv * wcol[H_ + tid];
            float gg = gb[2 * H_ + tid] + xv * wcol[2 * H_ + tid];
            float go = gb[3 * H_ + tid] + xv * wcol[3 * H_ + tid];
            float c  = fast_sig(gf) * c0s[tid] + fast_sig(gi) * ref_tanh(gg);
            float h  = fast_sig(go) * ref_tanh(c);
            r0s[tid] = fmaxf(h, 0.f);
        }
        __syncthreads();
        for (int base = wid * 4; base < 100; base += 64) {
            int r = base + q;
            const float* w = dsm + DW1 + r * 200;
            float acc = 0.f;
            #pragma unroll
            for (int k = kl; k < H_; k += 8) acc += r0s[k] * w[k];
            acc = qred(acc);
            if (kl == 0) l1s[r] = fmaxf(acc + b1s[r], 0.f);
        }
        __syncthreads();
        {
            int base = wid * 4;
            if (base < 52) {
                int r = base + q;
                float acc = 0.f;
                if (r < 50) {
                    const float* w = dsm + DW2 + r * 104;
                    #pragma unroll
                    for (int k = kl; k < 100; k += 8) acc += l1s[k] * w[k];
                }
                acc = qred(acc);
                if (kl == 0 && r < 50) l2s[r] = fmaxf(acc + b2s[r], 0.f);
            }
        }
        __syncthreads();
        if (wid == 0) {
            float acc = 0.f;
            #pragma unroll
            for (int k = lid; k < 50; k += 32) acc += l2s[k] * dsm[DW3 + k];
            acc = wred(acc);
            if (lid == 0) { float y = acc + b3s; out[b * 5 + st] = y; xs = y; }
        }
        __syncthreads();
        xv = xs;
    }
}

extern "C" void kernel_launch(void* const* d_in, const int* in_sizes, int n_in,
                              void* d_out, int out_size) {
    const float* x   = (const float*)d_in[0];
    const float* h0  = (const float*)d_in[1];
    const float* c0  = (const float*)d_in[2];
    const float* enc = (const float*)d_in[3];
    const float* Wa  = (const float*)d_in[4];
    const float* ba  = (const float*)d_in[5];
    const float* Ua  = (const float*)d_in[6];
    const float* bua = (const float*)d_in[7];
    const float* Va  = (const float*)d_in[8];
    const float* bva = (const float*)d_in[9];
    const float* Wih = (const float*)d_in[10];
    const float* Whh = (const float*)d_in[11];
    const float* bih = (const float*)d_in[12];
    const float* bhh = (const float*)d_in[13];
    const float* W1  = (const float*)d_in[14];
    const float* b1  = (const float*)d_in[15];
    const float* W2  = (const float*)d_in[16];
    const float* b2  = (const float*)d_in[17];
    const float* W3  = (const float*)d_in[18];
    const float* b3  = (const float*)d_in[19];
    float* out = (float*)d_out;

    // Uniform smem carveout across ALL kernels -> no per-node SM reconfiguration
    cudaFuncSetAttribute(prep_k,    cudaFuncAttributePreferredSharedMemoryCarveout, 100);
    cudaFuncSetAttribute(scores_k,  cudaFuncAttributePreferredSharedMemoryCarveout, 100);
    cudaFuncSetAttribute(softmax_k, cudaFuncAttributePreferredSharedMemoryCarveout, 100);
    cudaFuncSetAttribute(ctx_k,     cudaFuncAttributePreferredSharedMemoryCarveout, 100);
    cudaFuncSetAttribute(gates_k,   cudaFuncAttributePreferredSharedMemoryCarveout, 100);
    cudaFuncSetAttribute(decoder_k, cudaFuncAttributePreferredSharedMemoryCarveout, 100);
    cudaFuncSetAttribute(scores_k,  cudaFuncAttributeMaxDynamicSharedMemorySize, SM2_TOT);
    cudaFuncSetAttribute(decoder_k, cudaFuncAttributeMaxDynamicSharedMemorySize, DSM_TOT);

    prep_k<<<HP + B_, 512>>>(Ua, h0, Wa, ba, bua, Whh, bhh);   // launch 1
    scores_k<<<B_ * 32, 256, SM2_TOT>>>(enc, Va, bva);         // launch 2
    softmax_k<<<B_, 256>>>();                                  // launch 3
    ctx_k<<<dim3(B_, NCHUNK), 512>>>(enc);                     // launch 4 <- profiled
    gates_k<<<dim3(B_, 8), 256>>>(Wih, bih);                   // launch 5
    decoder_k<<<B_, 512, DSM_TOT>>>(x, c0, Wih, W1, b1, W2, b2, W3, b3, out);  // launch 6
}